// round 12
// baseline (speedup 1.0000x reference)
#include <cuda_runtime.h>
#include <cuda_bf16.h>

#define E_EDGES 262144
#define DMODEL  128
#define NNODES  65536
#define LN_EPSF 1e-5f
#define SCALEF  0.17677669529663687f   // 1/sqrt(32)
#define NTILES  2048                   // 128-edge tiles
#define PGRID   152

// ---------------- scratch (device globals; no allocations allowed) ----------
__device__ float g_S[(size_t)NNODES * DMODEL];       // sum exp(s)*V per node
__device__ float g_den[(size_t)NNODES * 4];          // sum exp(s) per node/head
__device__ float g_T[(size_t)NNODES * DMODEL];       // (0.5*S/den) @ Wo per node
__device__ __nv_bfloat16 g_Wb[4][DMODEL][DMODEL];    // bf16, transposed, paired-k+swz
__device__ int   g_is64;

// ---------------- helpers ----------------------------------------------------
__device__ __forceinline__ void mma_bf16(float c[4], const unsigned a[4],
                                         unsigned b0, unsigned b1) {
    asm volatile(
        "mma.sync.aligned.m16n8k16.row.col.f32.bf16.bf16.f32 "
        "{%0,%1,%2,%3}, {%4,%5,%6,%7}, {%8,%9}, {%0,%1,%2,%3};"
        : "+f"(c[0]), "+f"(c[1]), "+f"(c[2]), "+f"(c[3])
        : "r"(a[0]), "r"(a[1]), "r"(a[2]), "r"(a[3]), "r"(b0), "r"(b1));
}

__device__ __forceinline__ void ldsm4(unsigned r[4], unsigned addr) {
    asm volatile("ldmatrix.sync.aligned.m8n8.x4.shared.b16 {%0,%1,%2,%3}, [%4];"
                 : "=r"(r[0]), "=r"(r[1]), "=r"(r[2]), "=r"(r[3]) : "r"(addr));
}

__device__ __forceinline__ unsigned pack_bf16(float lo, float hi) {
    __nv_bfloat162 h = __floats2bfloat162_rn(lo, hi);   // .x = lo (low 16 bits)
    return *(unsigned*)&h;
}

__device__ __forceinline__ void red_add_v4(float* p, float x, float y, float z, float w) {
    asm volatile("red.global.add.v4.f32 [%0], {%1,%2,%3,%4};"
                 :: "l"(p), "f"(x), "f"(y), "f"(z), "f"(w) : "memory");
}
__device__ __forceinline__ void red_add_f(float* p, float v) {
    asm volatile("red.global.add.f32 [%0], %1;" :: "l"(p), "f"(v) : "memory");
}

__device__ __forceinline__ void cp_async16(void* smem_dst, const void* gsrc) {
    unsigned s = (unsigned)__cvta_generic_to_shared(smem_dst);
    asm volatile("cp.async.cg.shared.global [%0], [%1], 16;" :: "r"(s), "l"(gsrc));
}
__device__ __forceinline__ void cp_commit() {
    asm volatile("cp.async.commit_group;");
}
template <int N>
__device__ __forceinline__ void cp_wait() {
    asm volatile("cp.async.wait_group %0;" :: "n"(N));
}

__device__ __forceinline__ int node_of(const void* idx, int is64, size_t pos) {
    return is64 ? (int)__ldg((const long long*)idx + pos)
                : __ldg((const int*)idx + pos);
}

__device__ __forceinline__ int swzB(int n) {        // B quantum swizzle
    return ((n & 1) << 2) | ((n >> 1) & 3);
}

// bf16 GEMM core over a bf16 A tile (256B rows, quantum^(r&7) swizzle) and G
// weight matrices (paired-k layout). Per warp: m = 16*M rows, n32.
// A via ldmatrix.x4; B via one LDS.128 per (g,ni) covering TWO k16 steps.
template <int G, int M>
__device__ __forceinline__ void gemm_bf16(unsigned asB,
                                          const __nv_bfloat16* W0,
                                          const __nv_bfloat16* W1,
                                          const __nv_bfloat16* W2,
                                          float acc[G][M][4][4],
                                          int mbase, int wn, int lane) {
    const __nv_bfloat16* Wg[3] = {W0, W1, W2};
    int tg = lane & 3, gr = lane >> 2;
    int li = lane & 7, lj = (lane >> 3) & 1, qb = lane >> 4;
    int arow = mbase + lj * 8 + li;                 // mbase multiple of 16
    int rsw = arow & 7;
    unsigned aBase = asB + (unsigned)arow * 256u;

    #pragma unroll
    for (int g = 0; g < G; ++g)
        #pragma unroll
        for (int mi = 0; mi < M; ++mi)
            #pragma unroll
            for (int ni = 0; ni < 4; ++ni)
                #pragma unroll
                for (int q = 0; q < 4; ++q) acc[g][mi][ni][q] = 0.f;

    #pragma unroll
    for (int p = 0; p < 4; ++p) {                   // k32 groups
        float4 bf[G][4];
        #pragma unroll
        for (int g = 0; g < G; ++g)
            #pragma unroll
            for (int ni = 0; ni < 4; ++ni) {
                int n = wn * 32 + ni * 8 + gr;
                bf[g][ni] = *(const float4*)((const char*)Wg[g] + n * 256 +
                              (((p * 4 + tg) ^ swzB(n)) << 4));
            }
        #pragma unroll
        for (int sh = 0; sh < 2; ++sh) {            // two k16 steps per group
            int s = p * 2 + sh;
            unsigned koff = (unsigned)(((2 * s + qb) ^ rsw) << 4);
            unsigned a[M][4];
            #pragma unroll
            for (int mi = 0; mi < M; ++mi)
                ldsm4(a[mi], aBase + (unsigned)(mi * 16 * 256) + koff);
            #pragma unroll
            for (int g = 0; g < G; ++g)
                #pragma unroll
                for (int ni = 0; ni < 4; ++ni) {
                    unsigned b0 = __float_as_uint(sh ? bf[g][ni].z : bf[g][ni].x);
                    unsigned b1 = __float_as_uint(sh ? bf[g][ni].w : bf[g][ni].y);
                    #pragma unroll
                    for (int mi = 0; mi < M; ++mi)
                        mma_bf16(acc[g][mi][ni], a[mi], b0, b1);
                }
        }
    }
}

// ---------------- kernel 0: edge_index dtype detection ----------------------
__global__ void detect_kernel(const int* __restrict__ idx) {
    if (threadIdx.x == 0) {
        int nz = 0;
        #pragma unroll 1
        for (int i = 0; i < 64; ++i) nz |= idx[2 * i + 1];
        g_is64 = (nz == 0) ? 1 : 0;
    }
}

// ---------------- kernel 1: zero init ----------------------------------------
__global__ void init_kernel() {
    size_t i = (size_t)blockIdx.x * blockDim.x + threadIdx.x;
    if (i < (size_t)NNODES * DMODEL / 4)
        ((float4*)g_S)[i] = make_float4(0.f, 0.f, 0.f, 0.f);
    if (i < (size_t)NNODES)
        ((float4*)g_den)[i] = make_float4(0.f, 0.f, 0.f, 0.f);
}

// ---------------- kernel 2: weight prep --------------------------------------
// W^T[n][k] in bf16 with paired-k permutation (within each k32 group:
// newr = ((r>>1)&3)*8 + (r>>3)*2 + (r&1)) and quantum swizzle ^swzB(n).
__global__ void prep_kernel(const float* __restrict__ Wq, const float* __restrict__ Wk,
                            const float* __restrict__ Wv, const float* __restrict__ Wo) {
    __shared__ float t[32][33];
    const float* W[4] = {Wq, Wk, Wv, Wo};
    int w = blockIdx.z, k0 = blockIdx.x * 32, n0 = blockIdx.y * 32;
    int tx = threadIdx.x, ty = threadIdx.y;      // 32 x 8
    const float* src = W[w];
    #pragma unroll
    for (int j = 0; j < 32; j += 8)
        t[ty + j][tx] = src[(k0 + ty + j) * DMODEL + n0 + tx];
    __syncthreads();
    #pragma unroll
    for (int j = 0; j < 32; j += 8) {
        int n = n0 + ty + j;
        int k = k0 + tx;
        int r = k & 31;
        int newr = ((r >> 1) & 3) * 8 + ((r >> 3) << 1) + (r & 1);
        int klog = (k & ~31) | newr;
        int kphys = ((klog >> 3) ^ swzB(n)) * 8 + (klog & 7);
        g_Wb[w][n][kphys] = __float2bfloat16(t[tx][ty + j]);
    }
}

// ---------------- kernel 3: persistent fused QKV + scores + scatter ----------
// 152 CTAs x 512 thr (16 warps). 128-edge tiles. Warp grid 4m x 4n, per-warp
// m32 x n32, single-pass G=3 GEMM (Q,K,V together). Weights (96KB bf16)
// resident; X staged fp32 via cp.async, converted to bf16 after tile sync.
__global__ __launch_bounds__(512, 1)
void fusedP_kernel(const float* __restrict__ X, const void* __restrict__ idx,
                   const float* __restrict__ bq, const float* __restrict__ bk,
                   const float* __restrict__ bv) {
    extern __shared__ char smc[];
    __nv_bfloat16* As  = (__nv_bfloat16*)smc;              // [128][128] bf16
    __nv_bfloat16* Wq_ = As + 128 * 128;                   // 3 x [128][128] bf16
    __nv_bfloat16* Wk_ = Wq_ + 128 * 128;
    __nv_bfloat16* Wv_ = Wk_ + 128 * 128;
    float* Xs = (float*)(Wv_ + 128 * 128);                 // [128][128] fp32 staging

    int tid = threadIdx.x, lane = tid & 31, warp = tid >> 5;
    int wm = warp & 3, wn = warp >> 2, gr = lane >> 2, tg = lane & 3;
    int mbase = wm * 32;
    int is64 = g_is64;
    unsigned asB = (unsigned)__cvta_generic_to_shared(As);

    // one-time: 3 weight matrices (contiguous) + first X tile into staging
    for (int i = tid; i < 6144; i += 512)
        cp_async16((float*)Wq_ + i * 4, (const float*)g_Wb + i * 4);
    {
        size_t e0 = (size_t)blockIdx.x * 128;
        for (int i = tid; i < 4096; i += 512) {
            int r = i >> 5, c = (i & 31) << 2;
            cp_async16(Xs + r * 128 + c, X + (e0 + r) * DMODEL + c);
        }
    }
    cp_commit();
    cp_wait<0>();
    __syncthreads();

    // conversion roles: thread -> row pr, 4 quanta starting at qs
    int pr = tid >> 2, qs = (tid & 3) * 4;
    {   // build first As from staging
        #pragma unroll
        for (int j = 0; j < 4; ++j) {
            int q = qs + j;
            float4 x0 = *(const float4*)(Xs + pr * 128 + q * 8);
            float4 x1 = *(const float4*)(Xs + pr * 128 + q * 8 + 4);
            uint4 u;
            u.x = pack_bf16(x0.x, x0.y); u.y = pack_bf16(x0.z, x0.w);
            u.z = pack_bf16(x1.x, x1.y); u.w = pack_bf16(x1.z, x1.w);
            *(uint4*)((char*)As + pr * 256 + ((q ^ (pr & 7)) << 4)) = u;
        }
    }
    __syncthreads();

    // loop-invariant bias fragments (fp32, added post-GEMM)
    float2 bqr[4], bkr[4], bvr[4];
    #pragma unroll
    for (int ni = 0; ni < 4; ++ni) {
        int col = wn * 32 + ni * 8 + tg * 2;
        bqr[ni] = make_float2(__ldg(bq + col), __ldg(bq + col + 1));
        bkr[ni] = make_float2(__ldg(bk + col), __ldg(bk + col + 1));
        bvr[ni] = make_float2(__ldg(bv + col), __ldg(bv + col + 1));
    }

    for (int t = blockIdx.x; t < NTILES; t += PGRID) {
        size_t e0 = (size_t)t * 128;
        int tn = t + PGRID;
        bool hasNext = tn < NTILES;

        // stream next X tile (fp32) into staging while we compute
        if (hasNext) {
            size_t en = (size_t)tn * 128;
            for (int i = tid; i < 4096; i += 512) {
                int r = i >> 5, c = (i & 31) << 2;
                cp_async16(Xs + r * 128 + c, X + (en + r) * DMODEL + c);
            }
            cp_commit();
        }

        // prefetch this tile's edge indices
        int srcR[2][2], dstR[2][2];
        #pragma unroll
        for (int mi = 0; mi < 2; ++mi)
            #pragma unroll
            for (int sr = 0; sr < 2; ++sr) {
                int row = mbase + mi * 16 + sr * 8 + gr;
                srcR[mi][sr] = node_of(idx, is64, e0 + row);
                dstR[mi][sr] = node_of(idx, is64, (size_t)E_EDGES + e0 + row);
            }

        // single-pass triple GEMM: acc[0]=Q, acc[1]=K, acc[2]=V
        float acc[3][2][4][4];
        gemm_bf16<3, 2>(asB, Wq_, Wk_, Wv_, acc, mbase, wn, lane);

        // scores for head wn: (Q+bq).(K+bk), quad shuffle, exp
        float ev[4];
        #pragma unroll
        for (int mi = 0; mi < 2; ++mi) {
            float s0 = 0.f, s1 = 0.f;
            #pragma unroll
            for (int ni = 0; ni < 4; ++ni) {
                s0 += (acc[0][mi][ni][0] + bqr[ni].x) * (acc[1][mi][ni][0] + bkr[ni].x)
                    + (acc[0][mi][ni][1] + bqr[ni].y) * (acc[1][mi][ni][1] + bkr[ni].y);
                s1 += (acc[0][mi][ni][2] + bqr[ni].x) * (acc[1][mi][ni][2] + bkr[ni].x)
                    + (acc[0][mi][ni][3] + bqr[ni].y) * (acc[1][mi][ni][3] + bkr[ni].y);
            }
            s0 += __shfl_xor_sync(0xffffffffu, s0, 1);
            s0 += __shfl_xor_sync(0xffffffffu, s0, 2);
            s1 += __shfl_xor_sync(0xffffffffu, s1, 1);
            s1 += __shfl_xor_sync(0xffffffffu, s1, 2);
            ev[mi * 2]     = __expf(s0 * SCALEF);
            ev[mi * 2 + 1] = __expf(s1 * SCALEF);
        }

        __syncthreads();          // all warps done reading As

        // convert staged X -> As (bf16, swizzled)
        if (hasNext) {
            cp_wait<0>();
            #pragma unroll
            for (int j = 0; j < 4; ++j) {
                int q = qs + j;
                float4 x0 = *(const float4*)(Xs + pr * 128 + q * 8);
                float4 x1 = *(const float4*)(Xs + pr * 128 + q * 8 + 4);
                uint4 u;
                u.x = pack_bf16(x0.x, x0.y); u.y = pack_bf16(x0.z, x0.w);
                u.z = pack_bf16(x1.x, x1.y); u.w = pack_bf16(x1.z, x1.w);
                *(uint4*)((char*)As + pr * 256 + ((q ^ (pr & 7)) << 4)) = u;
            }
        }

        // scatter: weighted V to src & dst, den per head (fire-and-forget)
        #pragma unroll
        for (int mi = 0; mi < 2; ++mi) {
            #pragma unroll
            for (int sr = 0; sr < 2; ++sr) {
                int src = srcR[mi][sr], dst = dstR[mi][sr];
                float* ps = g_S + (size_t)src * DMODEL;
                float* pd = g_S + (size_t)dst * DMODEL;
                float w = ev[mi * 2 + sr];
                if (tg == 0) {
                    red_add_f(&g_den[(size_t)src * 4 + wn], w);
                    red_add_f(&g_den[(size_t)dst * 4 + wn], w);
                }
                #pragma unroll
                for (int ni = 0; ni < 4; ++ni) {
                    int col = wn * 32 + ni * 8 + tg * 2;
                    float v0 = (acc[2][mi][ni][sr * 2]     + bvr[ni].x) * w;
                    float v1 = (acc[2][mi][ni][sr * 2 + 1] + bvr[ni].y) * w;
                    float p0 = __shfl_xor_sync(0xffffffffu, v0, 1);
                    float p1 = __shfl_xor_sync(0xffffffffu, v1, 1);
                    if (!(tg & 1)) {
                        red_add_v4(ps + col, v0, v1, p0, p1);
                        red_add_v4(pd + col, v0, v1, p0, p1);
                    }
                }
            }
        }

        __syncthreads();          // As refilled
    }
}

// ---------------- kernel 4: per-NODE Wo GEMM: T = (0.5*S/den) @ Wo -----------
// 64-row node tiles, bf16 core, 48KB smem -> 2 CTAs/SM, 256 thr (2m x 4n, M=2).
__global__ __launch_bounds__(256, 2)
void nodeT_kernel() {
    extern __shared__ char smc[];
    __nv_bfloat16* Ms  = (__nv_bfloat16*)smc;      // [64][128] bf16 msg tile
    __nv_bfloat16* Wo_ = Ms + 64 * 128;            // [128][128] bf16 Wo

    int tid = threadIdx.x, lane = tid & 31, warp = tid >> 5;
    int wm = warp & 1, wn = warp >> 1, gr = lane >> 2, tg = lane & 3;
    size_t n0 = (size_t)blockIdx.x * 64;
    unsigned msB = (unsigned)__cvta_generic_to_shared(Ms);

    for (int i = tid; i < 2048; i += 256)
        cp_async16((float*)Wo_ + i * 4, (const float*)g_Wb[3] + i * 4);
    cp_commit();

    {   // build tile: 4 threads per row, one head (32 cols = 4 quanta) each
        int r = tid >> 2, hd = tid & 3;
        size_t node = n0 + r;
        float d = g_den[node * 4 + hd];
        float f = (d > 0.f) ? 0.5f / d : 0.f;
        const float* Sp = g_S + node * DMODEL + hd * 32;
        #pragma unroll
        for (int j = 0; j < 4; ++j) {
            int q = hd * 4 + j;
            float4 a = *(const float4*)(Sp + j * 8);
            float4 b = *(const float4*)(Sp + j * 8 + 4);
            uint4 u;
            u.x = pack_bf16(a.x * f, a.y * f); u.y = pack_bf16(a.z * f, a.w * f);
            u.z = pack_bf16(b.x * f, b.y * f); u.w = pack_bf16(b.z * f, b.w * f);
            *(uint4*)((char*)Ms + r * 256 + ((q ^ (r & 7)) << 4)) = u;
        }
    }
    cp_wait<0>();
    __syncthreads();

    float acc[1][2][4][4];
    gemm_bf16<1, 2>(msB, Wo_, Wo_, Wo_, acc, wm * 32, wn, lane);

    #pragma unroll
    for (int mi = 0; mi < 2; ++mi) {
        int r0 = wm * 32 + mi * 16 + gr;
        #pragma unroll
        for (int ni = 0; ni < 4; ++ni) {
            int col = wn * 32 + ni * 8 + tg * 2;
            *(float2*)(g_T + (n0 + r0) * DMODEL + col)     = make_float2(acc[0][mi][ni][0], acc[0][mi][ni][1]);
            *(float2*)(g_T + (n0 + r0 + 8) * DMODEL + col) = make_float2(acc[0][mi][ni][2], acc[0][mi][ni][3]);
        }
    }
}

// ---------------- kernel 5: edge epilogue: LN(T[src]+T[dst]+bo+X) ------------
__global__ __launch_bounds__(256)
void epi_kernel(const void* __restrict__ idx, const float* __restrict__ X,
                const float* __restrict__ bo, const float* __restrict__ gamma,
                const float* __restrict__ beta, float* __restrict__ out) {
    int tid = threadIdx.x, lane = tid & 31;
    size_t e = (size_t)blockIdx.x * 8 + (tid >> 5);
    int is64 = g_is64;

    int src = node_of(idx, is64, e);
    int dst = node_of(idx, is64, (size_t)E_EDGES + e);

    int c = lane * 4;
    float4 ts = *(const float4*)(g_T + (size_t)src * DMODEL + c);
    float4 td = *(const float4*)(g_T + (size_t)dst * DMODEL + c);
    float4 x4 = *(const float4*)(X + e * DMODEL + c);
    float4 b4 = *(const float4*)(bo + c);

    float4 v;
    v.x = ts.x + td.x + b4.x + x4.x;
    v.y = ts.y + td.y + b4.y + x4.y;
    v.z = ts.z + td.z + b4.z + x4.z;
    v.w = ts.w + td.w + b4.w + x4.w;

    float s = v.x + v.y + v.z + v.w;
    float q = v.x * v.x + v.y * v.y + v.z * v.z + v.w * v.w;
    #pragma unroll
    for (int o = 16; o > 0; o >>= 1) {
        s += __shfl_xor_sync(0xffffffffu, s, o);
        q += __shfl_xor_sync(0xffffffffu, q, o);
    }
    float mu = s * (1.0f / 128.0f);
    float var = q * (1.0f / 128.0f) - mu * mu;
    float rstd = rsqrtf(var + LN_EPSF);

    float4 g4 = *(const float4*)(gamma + c);
    float4 be = *(const float4*)(beta + c);
    float4 o4;
    o4.x = (v.x - mu) * rstd * g4.x + be.x;
    o4.y = (v.y - mu) * rstd * g4.y + be.y;
    o4.z = (v.z - mu) * rstd * g4.z + be.z;
    o4.w = (v.w - mu) * rstd * g4.w + be.w;
    *(float4*)(out + e * DMODEL + c) = o4;
}

// ---------------- host -------------------------------------------------------
#define SMEM_P     ((128 * 128 + 3 * 128 * 128) * 2 + 128 * 128 * 4)  // 128KB + 64KB
#define SMEM_NODE  ((64 * 128 + 128 * 128) * 2)                        // 48KB

extern "C" void kernel_launch(void* const* d_in, const int* in_sizes, int n_in,
                              void* d_out, int out_size) {
    const float* X   = (const float*)d_in[0];
    const void*  idx = d_in[1];
    int base = 2;
    if (n_in >= 13 && in_sizes[2] == 1) base = 3;
    const float* Wq    = (const float*)d_in[base + 0];
    const float* bq    = (const float*)d_in[base + 1];
    const float* Wk    = (const float*)d_in[base + 2];
    const float* bk    = (const float*)d_in[base + 3];
    const float* Wv    = (const float*)d_in[base + 4];
    const float* bv    = (const float*)d_in[base + 5];
    const float* Wo    = (const float*)d_in[base + 6];
    const float* bo    = (const float*)d_in[base + 7];
    const float* gamma = (const float*)d_in[base + 8];
    const float* beta  = (const float*)d_in[base + 9];
    float* out = (float*)d_out;

    cudaFuncSetAttribute(fusedP_kernel, cudaFuncAttributeMaxDynamicSharedMemorySize, SMEM_P);
    cudaFuncSetAttribute(nodeT_kernel,  cudaFuncAttributeMaxDynamicSharedMemorySize, SMEM_NODE);

    detect_kernel<<<1, 32>>>((const int*)idx);
    init_kernel<<<8192, 256>>>();
    prep_kernel<<<dim3(4, 4, 4), dim3(32, 8)>>>(Wq, Wk, Wv, Wo);
    fusedP_kernel<<<PGRID, 512, SMEM_P>>>(X, idx, bq, bk, bv);
    nodeT_kernel<<<NNODES / 64, 256, SMEM_NODE>>>();
    epi_kernel<<<E_EDGES / 8, 256>>>(idx, X, bo, gamma, beta, out);
}

// round 13
// speedup vs baseline: 1.0752x; 1.0752x over previous
#include <cuda_runtime.h>
#include <cuda_bf16.h>

#define E_EDGES 262144
#define DMODEL  128
#define NNODES  65536
#define LN_EPSF 1e-5f
#define SCALEF  0.17677669529663687f   // 1/sqrt(32)
#define NTILES  2048                   // 128-edge tiles
#define PGRID   152

// ---------------- scratch (device globals; no allocations allowed) ----------
__device__ float g_S[(size_t)NNODES * DMODEL];       // sum exp(s)*V per node
__device__ float g_den[(size_t)NNODES * 4];          // sum exp(s) per node/head
__device__ float g_T[(size_t)NNODES * DMODEL];       // (0.5*S/den) @ Wo per node
__device__ __nv_bfloat16 g_Wb[4][DMODEL][DMODEL];    // bf16, transposed, paired-k+swz
__device__ int   g_is64;

// ---------------- helpers ----------------------------------------------------
__device__ __forceinline__ void mma_bf16(float c[4], const unsigned a[4],
                                         unsigned b0, unsigned b1) {
    asm volatile(
        "mma.sync.aligned.m16n8k16.row.col.f32.bf16.bf16.f32 "
        "{%0,%1,%2,%3}, {%4,%5,%6,%7}, {%8,%9}, {%0,%1,%2,%3};"
        : "+f"(c[0]), "+f"(c[1]), "+f"(c[2]), "+f"(c[3])
        : "r"(a[0]), "r"(a[1]), "r"(a[2]), "r"(a[3]), "r"(b0), "r"(b1));
}

__device__ __forceinline__ void ldsm4(unsigned r[4], unsigned addr) {
    asm volatile("ldmatrix.sync.aligned.m8n8.x4.shared.b16 {%0,%1,%2,%3}, [%4];"
                 : "=r"(r[0]), "=r"(r[1]), "=r"(r[2]), "=r"(r[3]) : "r"(addr));
}

__device__ __forceinline__ unsigned pack_bf16(float lo, float hi) {
    __nv_bfloat162 h = __floats2bfloat162_rn(lo, hi);   // .x = lo (low 16 bits)
    return *(unsigned*)&h;
}

__device__ __forceinline__ void red_add_v4(float* p, float x, float y, float z, float w) {
    asm volatile("red.global.add.v4.f32 [%0], {%1,%2,%3,%4};"
                 :: "l"(p), "f"(x), "f"(y), "f"(z), "f"(w) : "memory");
}
__device__ __forceinline__ void red_add_f(float* p, float v) {
    asm volatile("red.global.add.f32 [%0], %1;" :: "l"(p), "f"(v) : "memory");
}

__device__ __forceinline__ void cp_async16(void* smem_dst, const void* gsrc) {
    unsigned s = (unsigned)__cvta_generic_to_shared(smem_dst);
    asm volatile("cp.async.cg.shared.global [%0], [%1], 16;" :: "r"(s), "l"(gsrc));
}
__device__ __forceinline__ void cp_commit() {
    asm volatile("cp.async.commit_group;");
}
template <int N>
__device__ __forceinline__ void cp_wait() {
    asm volatile("cp.async.wait_group %0;" :: "n"(N));
}

__device__ __forceinline__ int node_of(const void* idx, int is64, size_t pos) {
    return is64 ? (int)__ldg((const long long*)idx + pos)
                : __ldg((const int*)idx + pos);
}

__device__ __forceinline__ int swzB(int n) {        // B quantum swizzle
    return ((n & 1) << 2) | ((n >> 1) & 3);
}

// bf16 GEMM core over a bf16 A tile (256B rows, quantum^(r&7) swizzle) and G
// weight matrices (paired-k layout). Per warp: m = 16*M rows, n32.
// Register-pressure-aware ordering: per k32 group, A fragments for BOTH k16
// steps are loaded first, then each matrix's B fragments are loaded and
// consumed immediately (peak live: acc + 16 + 16 regs).
template <int G, int M>
__device__ __forceinline__ void gemm_bf16(unsigned asB,
                                          const __nv_bfloat16* W0,
                                          const __nv_bfloat16* W1,
                                          float acc[G][M][4][4],
                                          int mbase, int wn, int lane) {
    const __nv_bfloat16* Wg[2] = {W0, W1};
    int tg = lane & 3, gr = lane >> 2;
    int li = lane & 7, lj = (lane >> 3) & 1, qb = lane >> 4;
    int arow = mbase + lj * 8 + li;                 // mbase multiple of 16
    int rsw = arow & 7;
    unsigned aBase = asB + (unsigned)arow * 256u;

    #pragma unroll
    for (int g = 0; g < G; ++g)
        #pragma unroll
        for (int mi = 0; mi < M; ++mi)
            #pragma unroll
            for (int ni = 0; ni < 4; ++ni)
                #pragma unroll
                for (int q = 0; q < 4; ++q) acc[g][mi][ni][q] = 0.f;

    #pragma unroll
    for (int p = 0; p < 4; ++p) {                   // k32 groups
        // A fragments for both k16 steps of this group
        unsigned a[2][M][4];
        #pragma unroll
        for (int sh = 0; sh < 2; ++sh) {
            unsigned koff = (unsigned)(((p * 2 + sh) * 2 + qb) ^ rsw) << 4;
            #pragma unroll
            for (int mi = 0; mi < M; ++mi)
                ldsm4(a[sh][mi], aBase + (unsigned)(mi * 16 * 256) + koff);
        }
        // per matrix: load B, consume immediately
        #pragma unroll
        for (int g = 0; g < G; ++g) {
            float4 bf[4];
            #pragma unroll
            for (int ni = 0; ni < 4; ++ni) {
                int n = wn * 32 + ni * 8 + gr;
                bf[ni] = *(const float4*)((const char*)Wg[g] + n * 256 +
                           (((p * 4 + tg) ^ swzB(n)) << 4));
            }
            #pragma unroll
            for (int sh = 0; sh < 2; ++sh)
                #pragma unroll
                for (int ni = 0; ni < 4; ++ni) {
                    unsigned b0 = __float_as_uint(sh ? bf[ni].z : bf[ni].x);
                    unsigned b1 = __float_as_uint(sh ? bf[ni].w : bf[ni].y);
                    #pragma unroll
                    for (int mi = 0; mi < M; ++mi)
                        mma_bf16(acc[g][mi][ni], a[sh][mi], b0, b1);
                }
        }
    }
}

// ---------------- kernel 0: edge_index dtype detection ----------------------
__global__ void detect_kernel(const int* __restrict__ idx) {
    if (threadIdx.x == 0) {
        int nz = 0;
        #pragma unroll 1
        for (int i = 0; i < 64; ++i) nz |= idx[2 * i + 1];
        g_is64 = (nz == 0) ? 1 : 0;
    }
}

// ---------------- kernel 1: zero init ----------------------------------------
__global__ void init_kernel() {
    size_t i = (size_t)blockIdx.x * blockDim.x + threadIdx.x;
    if (i < (size_t)NNODES * DMODEL / 4)
        ((float4*)g_S)[i] = make_float4(0.f, 0.f, 0.f, 0.f);
    if (i < (size_t)NNODES)
        ((float4*)g_den)[i] = make_float4(0.f, 0.f, 0.f, 0.f);
}

// ---------------- kernel 2: weight prep --------------------------------------
// W^T[n][k] in bf16 with paired-k permutation (within each k32 group:
// newr = ((r>>1)&3)*8 + (r>>3)*2 + (r&1)) and quantum swizzle ^swzB(n).
__global__ void prep_kernel(const float* __restrict__ Wq, const float* __restrict__ Wk,
                            const float* __restrict__ Wv, const float* __restrict__ Wo) {
    __shared__ float t[32][33];
    const float* W[4] = {Wq, Wk, Wv, Wo};
    int w = blockIdx.z, k0 = blockIdx.x * 32, n0 = blockIdx.y * 32;
    int tx = threadIdx.x, ty = threadIdx.y;      // 32 x 8
    const float* src = W[w];
    #pragma unroll
    for (int j = 0; j < 32; j += 8)
        t[ty + j][tx] = src[(k0 + ty + j) * DMODEL + n0 + tx];
    __syncthreads();
    #pragma unroll
    for (int j = 0; j < 32; j += 8) {
        int n = n0 + ty + j;
        int k = k0 + tx;
        int r = k & 31;
        int newr = ((r >> 1) & 3) * 8 + ((r >> 3) << 1) + (r & 1);
        int klog = (k & ~31) | newr;
        int kphys = ((klog >> 3) ^ swzB(n)) * 8 + (klog & 7);
        g_Wb[w][n][kphys] = __float2bfloat16(t[tx][ty + j]);
    }
}

// ---------------- kernel 3: persistent fused QKV + scores + scatter ----------
// 152 CTAs x 512 thr (16 warps). 128-edge tiles. Warp grid 2m x 4n wgroups,
// per-warp m32 (M=2) x n32. Two GEMM passes: Q+K (G=2), then V (G=1) —
// keeps register peak under the 128-reg cap (R12 spill post-mortem).
__global__ __launch_bounds__(512, 1)
void fusedP_kernel(const float* __restrict__ X, const void* __restrict__ idx,
                   const float* __restrict__ bq, const float* __restrict__ bk,
                   const float* __restrict__ bv) {
    extern __shared__ char smc[];
    __nv_bfloat16* As  = (__nv_bfloat16*)smc;              // [128][128] bf16
    __nv_bfloat16* Wq_ = As + 128 * 128;                   // 3 x [128][128] bf16
    __nv_bfloat16* Wk_ = Wq_ + 128 * 128;
    __nv_bfloat16* Wv_ = Wk_ + 128 * 128;
    float* Xs = (float*)(Wv_ + 128 * 128);                 // [128][128] fp32 staging

    int tid = threadIdx.x, lane = tid & 31, warp = tid >> 5;
    int wm = warp & 1, wn = (warp >> 1) & 3, gr = lane >> 2, tg = lane & 3;
    int mbase = wm * 64 + (warp >> 3) * 32;                // 2 m-groups x {0,32}
    // NOTE: warp layout: bit0 = wm(64-row half), bits1-2 = wn(head), bit3 = 32-row sub
    int is64 = g_is64;
    unsigned asB = (unsigned)__cvta_generic_to_shared(As);

    // one-time: 3 weight matrices (contiguous) + first X tile into staging
    for (int i = tid; i < 6144; i += 512)
        cp_async16((float*)Wq_ + i * 4, (const float*)g_Wb + i * 4);
    {
        size_t e0 = (size_t)blockIdx.x * 128;
        for (int i = tid; i < 4096; i += 512) {
            int r = i >> 5, c = (i & 31) << 2;
            cp_async16(Xs + r * 128 + c, X + (e0 + r) * DMODEL + c);
        }
    }
    cp_commit();
    cp_wait<0>();
    __syncthreads();

    // conversion roles: thread -> row pr, 4 quanta starting at qs
    int pr = tid >> 2, qs = (tid & 3) * 4;
    {   // build first As from staging
        #pragma unroll
        for (int j = 0; j < 4; ++j) {
            int q = qs + j;
            float4 x0 = *(const float4*)(Xs + pr * 128 + q * 8);
            float4 x1 = *(const float4*)(Xs + pr * 128 + q * 8 + 4);
            uint4 u;
            u.x = pack_bf16(x0.x, x0.y); u.y = pack_bf16(x0.z, x0.w);
            u.z = pack_bf16(x1.x, x1.y); u.w = pack_bf16(x1.z, x1.w);
            *(uint4*)((char*)As + pr * 256 + ((q ^ (pr & 7)) << 4)) = u;
        }
    }
    __syncthreads();

    // loop-invariant bias fragments (fp32, added post-GEMM)
    float2 bqr[4], bkr[4], bvr[4];
    #pragma unroll
    for (int ni = 0; ni < 4; ++ni) {
        int col = wn * 32 + ni * 8 + tg * 2;
        bqr[ni] = make_float2(__ldg(bq + col), __ldg(bq + col + 1));
        bkr[ni] = make_float2(__ldg(bk + col), __ldg(bk + col + 1));
        bvr[ni] = make_float2(__ldg(bv + col), __ldg(bv + col + 1));
    }

    for (int t = blockIdx.x; t < NTILES; t += PGRID) {
        size_t e0 = (size_t)t * 128;
        int tn = t + PGRID;
        bool hasNext = tn < NTILES;

        // stream next X tile (fp32) into staging while we compute
        if (hasNext) {
            size_t en = (size_t)tn * 128;
            for (int i = tid; i < 4096; i += 512) {
                int r = i >> 5, c = (i & 31) << 2;
                cp_async16(Xs + r * 128 + c, X + (en + r) * DMODEL + c);
            }
            cp_commit();
        }

        // ---- pass 1: Q + K (G=2, M=2) ----
        float accQK[2][2][4][4];
        gemm_bf16<2, 2>(asB, Wq_, Wk_, accQK, mbase, wn, lane);

        // scores for head wn: (Q+bq).(K+bk), quad shuffle, exp
        float ev[4];
        #pragma unroll
        for (int mi = 0; mi < 2; ++mi) {
            float s0 = 0.f, s1 = 0.f;
            #pragma unroll
            for (int ni = 0; ni < 4; ++ni) {
                s0 += (accQK[0][mi][ni][0] + bqr[ni].x) * (accQK[1][mi][ni][0] + bkr[ni].x)
                    + (accQK[0][mi][ni][1] + bqr[ni].y) * (accQK[1][mi][ni][1] + bkr[ni].y);
                s1 += (accQK[0][mi][ni][2] + bqr[ni].x) * (accQK[1][mi][ni][2] + bkr[ni].x)
                    + (accQK[0][mi][ni][3] + bqr[ni].y) * (accQK[1][mi][ni][3] + bkr[ni].y);
            }
            s0 += __shfl_xor_sync(0xffffffffu, s0, 1);
            s0 += __shfl_xor_sync(0xffffffffu, s0, 2);
            s1 += __shfl_xor_sync(0xffffffffu, s1, 1);
            s1 += __shfl_xor_sync(0xffffffffu, s1, 2);
            ev[mi * 2]     = __expf(s0 * SCALEF);
            ev[mi * 2 + 1] = __expf(s1 * SCALEF);
        }

        // edge indices for this tile (latency hides under pass 2)
        int srcR[2][2], dstR[2][2];
        #pragma unroll
        for (int mi = 0; mi < 2; ++mi)
            #pragma unroll
            for (int sr = 0; sr < 2; ++sr) {
                int row = mbase + mi * 16 + sr * 8 + gr;
                srcR[mi][sr] = node_of(idx, is64, e0 + row);
                dstR[mi][sr] = node_of(idx, is64, (size_t)E_EDGES + e0 + row);
            }

        // ---- pass 2: V (G=1, M=2) ----
        float accV[1][2][4][4];
        gemm_bf16<1, 2>(asB, Wv_, Wv_, accV, mbase, wn, lane);

        __syncthreads();          // all warps done reading As

        // convert staged X -> As (bf16, swizzled)
        if (hasNext) {
            cp_wait<0>();
            #pragma unroll
            for (int j = 0; j < 4; ++j) {
                int q = qs + j;
                float4 x0 = *(const float4*)(Xs + pr * 128 + q * 8);
                float4 x1 = *(const float4*)(Xs + pr * 128 + q * 8 + 4);
                uint4 u;
                u.x = pack_bf16(x0.x, x0.y); u.y = pack_bf16(x0.z, x0.w);
                u.z = pack_bf16(x1.x, x1.y); u.w = pack_bf16(x1.z, x1.w);
                *(uint4*)((char*)As + pr * 256 + ((q ^ (pr & 7)) << 4)) = u;
            }
        }

        // scatter: weighted V to src & dst, den per head (fire-and-forget)
        #pragma unroll
        for (int mi = 0; mi < 2; ++mi) {
            #pragma unroll
            for (int sr = 0; sr < 2; ++sr) {
                int src = srcR[mi][sr], dst = dstR[mi][sr];
                float* ps = g_S + (size_t)src * DMODEL;
                float* pd = g_S + (size_t)dst * DMODEL;
                float w = ev[mi * 2 + sr];
                if (tg == 0) {
                    red_add_f(&g_den[(size_t)src * 4 + wn], w);
                    red_add_f(&g_den[(size_t)dst * 4 + wn], w);
                }
                #pragma unroll
                for (int ni = 0; ni < 4; ++ni) {
                    int col = wn * 32 + ni * 8 + tg * 2;
                    float v0 = (accV[0][mi][ni][sr * 2]     + bvr[ni].x) * w;
                    float v1 = (accV[0][mi][ni][sr * 2 + 1] + bvr[ni].y) * w;
                    float p0 = __shfl_xor_sync(0xffffffffu, v0, 1);
                    float p1 = __shfl_xor_sync(0xffffffffu, v1, 1);
                    if (!(tg & 1)) {
                        red_add_v4(ps + col, v0, v1, p0, p1);
                        red_add_v4(pd + col, v0, v1, p0, p1);
                    }
                }
            }
        }

        __syncthreads();          // As refilled
    }
}

// ---------------- kernel 4: per-NODE Wo GEMM: T = (0.5*S/den) @ Wo -----------
// 64-row node tiles, bf16 core, 48KB smem -> 2 CTAs/SM, 256 thr (2m x 4n, M=2).
__global__ __launch_bounds__(256, 2)
void nodeT_kernel() {
    extern __shared__ char smc[];
    __nv_bfloat16* Ms  = (__nv_bfloat16*)smc;      // [64][128] bf16 msg tile
    __nv_bfloat16* Wo_ = Ms + 64 * 128;            // [128][128] bf16 Wo

    int tid = threadIdx.x, lane = tid & 31, warp = tid >> 5;
    int wm = warp & 1, wn = warp >> 1, gr = lane >> 2, tg = lane & 3;
    size_t n0 = (size_t)blockIdx.x * 64;
    unsigned msB = (unsigned)__cvta_generic_to_shared(Ms);

    for (int i = tid; i < 2048; i += 256)
        cp_async16((float*)Wo_ + i * 4, (const float*)g_Wb[3] + i * 4);
    cp_commit();

    {   // build tile: 4 threads per row, one head (32 cols = 4 quanta) each
        int r = tid >> 2, hd = tid & 3;
        size_t node = n0 + r;
        float d = g_den[node * 4 + hd];
        float f = (d > 0.f) ? 0.5f / d : 0.f;
        const float* Sp = g_S + node * DMODEL + hd * 32;
        #pragma unroll
        for (int j = 0; j < 4; ++j) {
            int q = hd * 4 + j;
            float4 a = *(const float4*)(Sp + j * 8);
            float4 b = *(const float4*)(Sp + j * 8 + 4);
            uint4 u;
            u.x = pack_bf16(a.x * f, a.y * f); u.y = pack_bf16(a.z * f, a.w * f);
            u.z = pack_bf16(b.x * f, b.y * f); u.w = pack_bf16(b.z * f, b.w * f);
            *(uint4*)((char*)Ms + r * 256 + ((q ^ (r & 7)) << 4)) = u;
        }
    }
    cp_wait<0>();
    __syncthreads();

    float acc[1][2][4][4];
    gemm_bf16<1, 2>(msB, Wo_, Wo_, acc, wm * 32, wn, lane);

    #pragma unroll
    for (int mi = 0; mi < 2; ++mi) {
        int r0 = wm * 32 + mi * 16 + gr;
        #pragma unroll
        for (int ni = 0; ni < 4; ++ni) {
            int col = wn * 32 + ni * 8 + tg * 2;
            *(float2*)(g_T + (n0 + r0) * DMODEL + col)     = make_float2(acc[0][mi][ni][0], acc[0][mi][ni][1]);
            *(float2*)(g_T + (n0 + r0 + 8) * DMODEL + col) = make_float2(acc[0][mi][ni][2], acc[0][mi][ni][3]);
        }
    }
}

// ---------------- kernel 5: edge epilogue: LN(T[src]+T[dst]+bo+X) ------------
__global__ __launch_bounds__(256)
void epi_kernel(const void* __restrict__ idx, const float* __restrict__ X,
                const float* __restrict__ bo, const float* __restrict__ gamma,
                const float* __restrict__ beta, float* __restrict__ out) {
    int tid = threadIdx.x, lane = tid & 31;
    size_t e = (size_t)blockIdx.x * 8 + (tid >> 5);
    int is64 = g_is64;

    int src = node_of(idx, is64, e);
    int dst = node_of(idx, is64, (size_t)E_EDGES + e);

    int c = lane * 4;
    float4 ts = *(const float4*)(g_T + (size_t)src * DMODEL + c);
    float4 td = *(const float4*)(g_T + (size_t)dst * DMODEL + c);
    float4 x4 = *(const float4*)(X + e * DMODEL + c);
    float4 b4 = *(const float4*)(bo + c);

    float4 v;
    v.x = ts.x + td.x + b4.x + x4.x;
    v.y = ts.y + td.y + b4.y + x4.y;
    v.z = ts.z + td.z + b4.z + x4.z;
    v.w = ts.w + td.w + b4.w + x4.w;

    float s = v.x + v.y + v.z + v.w;
    float q = v.x * v.x + v.y * v.y + v.z * v.z + v.w * v.w;
    #pragma unroll
    for (int o = 16; o > 0; o >>= 1) {
        s += __shfl_xor_sync(0xffffffffu, s, o);
        q += __shfl_xor_sync(0xffffffffu, q, o);
    }
    float mu = s * (1.0f / 128.0f);
    float var = q * (1.0f / 128.0f) - mu * mu;
    float rstd = rsqrtf(var + LN_EPSF);

    float4 g4 = *(const float4*)(gamma + c);
    float4 be = *(const float4*)(beta + c);
    float4 o4;
    o4.x = (v.x - mu) * rstd * g4.x + be.x;
    o4.y = (v.y - mu) * rstd * g4.y + be.y;
    o4.z = (v.z - mu) * rstd * g4.z + be.z;
    o4.w = (v.w - mu) * rstd * g4.w + be.w;
    *(float4*)(out + e * DMODEL + c) = o4;
}

// ---------------- host -------------------------------------------------------
#define SMEM_P     ((128 * 128 + 3 * 128 * 128) * 2 + 128 * 128 * 4)  // 128KB + 64KB
#define SMEM_NODE  ((64 * 128 + 128 * 128) * 2)                        // 48KB

extern "C" void kernel_launch(void* const* d_in, const int* in_sizes, int n_in,
                              void* d_out, int out_size) {
    const float* X   = (const float*)d_in[0];
    const void*  idx = d_in[1];
    int base = 2;
    if (n_in >= 13 && in_sizes[2] == 1) base = 3;
    const float* Wq    = (const float*)d_in[base + 0];
    const float* bq    = (const float*)d_in[base + 1];
    const float* Wk    = (const float*)d_in[base + 2];
    const float* bk    = (const float*)d_in[base + 3];
    const float* Wv    = (const float*)d_in[base + 4];
    const float* bv    = (const float*)d_in[base + 5];
    const float* Wo    = (const float*)d_in[base + 6];
    const float* bo    = (const float*)d_in[base + 7];
    const float* gamma = (const float*)d_in[base + 8];
    const float* beta  = (const float*)d_in[base + 9];
    float* out = (float*)d_out;

    cudaFuncSetAttribute(fusedP_kernel, cudaFuncAttributeMaxDynamicSharedMemorySize, SMEM_P);
    cudaFuncSetAttribute(nodeT_kernel,  cudaFuncAttributeMaxDynamicSharedMemorySize, SMEM_NODE);

    detect_kernel<<<1, 32>>>((const int*)idx);
    init_kernel<<<8192, 256>>>();
    prep_kernel<<<dim3(4, 4, 4), dim3(32, 8)>>>(Wq, Wk, Wv, Wo);
    fusedP_kernel<<<PGRID, 512, SMEM_P>>>(X, idx, bq, bk, bv);
    nodeT_kernel<<<NNODES / 64, 256, SMEM_NODE>>>();
    epi_kernel<<<E_EDGES / 8, 256>>>(idx, X, bo, gamma, beta, out);
}

// round 14
// speedup vs baseline: 1.1390x; 1.0593x over previous
#include <cuda_runtime.h>
#include <cuda_bf16.h>

#define E_EDGES 262144
#define DMODEL  128
#define NNODES  65536
#define LN_EPSF 1e-5f
#define SCALEF  0.17677669529663687f   // 1/sqrt(32)
#define NTILES  4096                   // 64-edge tiles
#define PGRID   152

// ---------------- scratch (device globals; no allocations allowed) ----------
__device__ float g_S[(size_t)NNODES * DMODEL];       // sum exp(s)*V per node
__device__ float g_den[(size_t)NNODES * 4];          // sum exp(s) per node/head
__device__ float g_T[(size_t)NNODES * DMODEL];       // (0.5*S/den)@Wo + 0.5*bo
__device__ __nv_bfloat16 g_Wb[4][DMODEL][DMODEL];    // bf16, transposed, paired-k+swz
__device__ int   g_is64;

// ---------------- helpers ----------------------------------------------------
__device__ __forceinline__ void mma_bf16(float c[4], const unsigned a[4],
                                         unsigned b0, unsigned b1) {
    asm volatile(
        "mma.sync.aligned.m16n8k16.row.col.f32.bf16.bf16.f32 "
        "{%0,%1,%2,%3}, {%4,%5,%6,%7}, {%8,%9}, {%0,%1,%2,%3};"
        : "+f"(c[0]), "+f"(c[1]), "+f"(c[2]), "+f"(c[3])
        : "r"(a[0]), "r"(a[1]), "r"(a[2]), "r"(a[3]), "r"(b0), "r"(b1));
}

__device__ __forceinline__ void ldsm4(unsigned r[4], unsigned addr) {
    asm volatile("ldmatrix.sync.aligned.m8n8.x4.shared.b16 {%0,%1,%2,%3}, [%4];"
                 : "=r"(r[0]), "=r"(r[1]), "=r"(r[2]), "=r"(r[3]) : "r"(addr));
}

__device__ __forceinline__ unsigned pack_bf16(float lo, float hi) {
    __nv_bfloat162 h = __floats2bfloat162_rn(lo, hi);   // .x = lo (low 16 bits)
    return *(unsigned*)&h;
}

__device__ __forceinline__ void red_add_v4(float* p, float x, float y, float z, float w) {
    asm volatile("red.global.add.v4.f32 [%0], {%1,%2,%3,%4};"
                 :: "l"(p), "f"(x), "f"(y), "f"(z), "f"(w) : "memory");
}
__device__ __forceinline__ void red_add_f(float* p, float v) {
    asm volatile("red.global.add.f32 [%0], %1;" :: "l"(p), "f"(v) : "memory");
}

__device__ __forceinline__ void cp_async16(void* smem_dst, const void* gsrc) {
    unsigned s = (unsigned)__cvta_generic_to_shared(smem_dst);
    asm volatile("cp.async.cg.shared.global [%0], [%1], 16;" :: "r"(s), "l"(gsrc));
}
__device__ __forceinline__ void cp_commit() {
    asm volatile("cp.async.commit_group;");
}
template <int N>
__device__ __forceinline__ void cp_wait() {
    asm volatile("cp.async.wait_group %0;" :: "n"(N));
}

__device__ __forceinline__ int node_of(const void* idx, int is64, size_t pos) {
    return is64 ? (int)__ldg((const long long*)idx + pos)
                : __ldg((const int*)idx + pos);
}

__device__ __forceinline__ int swzB(int n) {        // B quantum swizzle
    return ((n & 1) << 2) | ((n >> 1) & 3);
}

// bf16 GEMM core over a 64-row A tile (bf16, 256B rows, quantum^(r&7) swizzle)
// and G weight matrices (paired-k layout). Per warp: m = 16*M rows, n32.
// A via ldmatrix.x4; B via one LDS.128 per (g,ni) covering TWO k16 steps.
template <int G, int M>
__device__ __forceinline__ void gemm_bf16(unsigned asB,
                                          const __nv_bfloat16* W0,
                                          const __nv_bfloat16* W1,
                                          float acc[G][M][4][4],
                                          int mbase, int wn, int lane) {
    const __nv_bfloat16* Wg[2] = {W0, W1};
    int tg = lane & 3, gr = lane >> 2;
    int li = lane & 7, lj = (lane >> 3) & 1, qb = lane >> 4;
    int arow = mbase + lj * 8 + li;                 // mbase multiple of 16
    int rsw = arow & 7;
    unsigned aBase = asB + (unsigned)arow * 256u;

    #pragma unroll
    for (int g = 0; g < G; ++g)
        #pragma unroll
        for (int mi = 0; mi < M; ++mi)
            #pragma unroll
            for (int ni = 0; ni < 4; ++ni)
                #pragma unroll
                for (int q = 0; q < 4; ++q) acc[g][mi][ni][q] = 0.f;

    #pragma unroll
    for (int p = 0; p < 4; ++p) {                   // k32 groups
        float4 bf[G][4];
        #pragma unroll
        for (int g = 0; g < G; ++g)
            #pragma unroll
            for (int ni = 0; ni < 4; ++ni) {
                int n = wn * 32 + ni * 8 + gr;
                bf[g][ni] = *(const float4*)((const char*)Wg[g] + n * 256 +
                              (((p * 4 + tg) ^ swzB(n)) << 4));
            }
        #pragma unroll
        for (int sh = 0; sh < 2; ++sh) {            // two k16 steps per group
            int s = p * 2 + sh;
            unsigned koff = (unsigned)(((2 * s + qb) ^ rsw) << 4);
            unsigned a[M][4];
            #pragma unroll
            for (int mi = 0; mi < M; ++mi)
                ldsm4(a[mi], aBase + (unsigned)(mi * 16 * 256) + koff);
            #pragma unroll
            for (int g = 0; g < G; ++g)
                #pragma unroll
                for (int ni = 0; ni < 4; ++ni) {
                    unsigned b0 = __float_as_uint(sh ? bf[g][ni].z : bf[g][ni].x);
                    unsigned b1 = __float_as_uint(sh ? bf[g][ni].w : bf[g][ni].y);
                    #pragma unroll
                    for (int mi = 0; mi < M; ++mi)
                        mma_bf16(acc[g][mi][ni], a[mi], b0, b1);
                }
        }
    }
}

// ---------------- kernel 0: edge_index dtype detection ----------------------
__global__ void detect_kernel(const int* __restrict__ idx) {
    if (threadIdx.x == 0) {
        int nz = 0;
        #pragma unroll 1
        for (int i = 0; i < 64; ++i) nz |= idx[2 * i + 1];
        g_is64 = (nz == 0) ? 1 : 0;
    }
}

// ---------------- kernel 1: zero init ----------------------------------------
__global__ void init_kernel() {
    size_t i = (size_t)blockIdx.x * blockDim.x + threadIdx.x;
    if (i < (size_t)NNODES * DMODEL / 4)
        ((float4*)g_S)[i] = make_float4(0.f, 0.f, 0.f, 0.f);
    if (i < (size_t)NNODES)
        ((float4*)g_den)[i] = make_float4(0.f, 0.f, 0.f, 0.f);
}

// ---------------- kernel 2: weight prep --------------------------------------
// W^T[n][k] in bf16 with paired-k permutation (within each k32 group:
// newr = ((r>>1)&3)*8 + (r>>3)*2 + (r&1)) and quantum swizzle ^swzB(n).
__global__ void prep_kernel(const float* __restrict__ Wq, const float* __restrict__ Wk,
                            const float* __restrict__ Wv, const float* __restrict__ Wo) {
    __shared__ float t[32][33];
    const float* W[4] = {Wq, Wk, Wv, Wo};
    int w = blockIdx.z, k0 = blockIdx.x * 32, n0 = blockIdx.y * 32;
    int tx = threadIdx.x, ty = threadIdx.y;      // 32 x 8
    const float* src = W[w];
    #pragma unroll
    for (int j = 0; j < 32; j += 8)
        t[ty + j][tx] = src[(k0 + ty + j) * DMODEL + n0 + tx];
    __syncthreads();
    #pragma unroll
    for (int j = 0; j < 32; j += 8) {
        int n = n0 + ty + j;
        int k = k0 + tx;
        int r = k & 31;
        int newr = ((r >> 1) & 3) * 8 + ((r >> 3) << 1) + (r & 1);
        int klog = (k & ~31) | newr;
        int kphys = ((klog >> 3) ^ swzB(n)) * 8 + (klog & 7);
        g_Wb[w][n][kphys] = __float2bfloat16(t[tx][ty + j]);
    }
}

// ---------------- kernel 3: persistent fused QKV + scores + scatter ----------
// 152 CTAs x 512 thr (16 warps). 64-edge tiles (R11-proven shape).
// Warp grid 4m x 4n, per-warp m16 x n32; Q+K pass then V pass.
// Scatter: split-target REDG (even lanes -> src, odd lanes -> dst).
__global__ __launch_bounds__(512, 1)
void fusedP_kernel(const float* __restrict__ X, const void* __restrict__ idx,
                   const float* __restrict__ bq, const float* __restrict__ bk,
                   const float* __restrict__ bv) {
    extern __shared__ char smc[];
    __nv_bfloat16* As  = (__nv_bfloat16*)smc;              // [64][128] bf16
    __nv_bfloat16* Wq_ = As + 64 * 128;                    // 3 x [128][128] bf16
    __nv_bfloat16* Wk_ = Wq_ + 128 * 128;
    __nv_bfloat16* Wv_ = Wk_ + 128 * 128;
    float* Xs = (float*)(Wv_ + 128 * 128);                 // [64][128] fp32 staging

    int tid = threadIdx.x, lane = tid & 31, warp = tid >> 5;
    int wm = warp & 3, wn = warp >> 2, gr = lane >> 2, tg = lane & 3;
    int mbase = wm * 16;
    int is64 = g_is64;
    unsigned asB = (unsigned)__cvta_generic_to_shared(As);

    // one-time: 3 weight matrices (contiguous) + first X tile into staging
    for (int i = tid; i < 6144; i += 512)
        cp_async16((float*)Wq_ + i * 4, (const float*)g_Wb + i * 4);
    {
        size_t e0 = (size_t)blockIdx.x * 64;
        for (int i = tid; i < 2048; i += 512) {
            int r = i >> 5, c = (i & 31) << 2;
            cp_async16(Xs + r * 128 + c, X + (e0 + r) * DMODEL + c);
        }
    }
    cp_commit();
    cp_wait<0>();
    __syncthreads();

    // conversion roles: thread -> (row pr, 2 quanta starting at qs)
    int pr = tid >> 3, qs = (tid & 7) * 2;
    {   // build first As from staging
        #pragma unroll
        for (int j = 0; j < 2; ++j) {
            int q = qs + j;
            float4 x0 = *(const float4*)(Xs + pr * 128 + q * 8);
            float4 x1 = *(const float4*)(Xs + pr * 128 + q * 8 + 4);
            uint4 u;
            u.x = pack_bf16(x0.x, x0.y); u.y = pack_bf16(x0.z, x0.w);
            u.z = pack_bf16(x1.x, x1.y); u.w = pack_bf16(x1.z, x1.w);
            *(uint4*)((char*)As + pr * 256 + ((q ^ (pr & 7)) << 4)) = u;
        }
    }
    __syncthreads();

    // loop-invariant bias fragments (fp32, added post-GEMM)
    float2 bqr[4], bkr[4], bvr[4];
    #pragma unroll
    for (int ni = 0; ni < 4; ++ni) {
        int col = wn * 32 + ni * 8 + tg * 2;
        bqr[ni] = make_float2(__ldg(bq + col), __ldg(bq + col + 1));
        bkr[ni] = make_float2(__ldg(bk + col), __ldg(bk + col + 1));
        bvr[ni] = make_float2(__ldg(bv + col), __ldg(bv + col + 1));
    }

    for (int t = blockIdx.x; t < NTILES; t += PGRID) {
        size_t e0 = (size_t)t * 64;
        int tn = t + PGRID;
        bool hasNext = tn < NTILES;

        // stream next X tile (fp32) into staging while we compute
        if (hasNext) {
            size_t en = (size_t)tn * 64;
            for (int i = tid; i < 2048; i += 512) {
                int r = i >> 5, c = (i & 31) << 2;
                cp_async16(Xs + r * 128 + c, X + (en + r) * DMODEL + c);
            }
            cp_commit();
        }

        // prefetch this tile's edge indices
        int srcR[2], dstR[2];
        #pragma unroll
        for (int sr = 0; sr < 2; ++sr) {
            int row = mbase + sr * 8 + gr;
            srcR[sr] = node_of(idx, is64, e0 + row);
            dstR[sr] = node_of(idx, is64, (size_t)E_EDGES + e0 + row);
        }

        // pass 1: Q + K
        float accQK[2][1][4][4];
        gemm_bf16<2, 1>(asB, Wq_, Wk_, accQK, mbase, wn, lane);

        // scores for head wn, exp
        float ev[2];
        {
            float s0 = 0.f, s1 = 0.f;
            #pragma unroll
            for (int ni = 0; ni < 4; ++ni) {
                s0 += (accQK[0][0][ni][0] + bqr[ni].x) * (accQK[1][0][ni][0] + bkr[ni].x)
                    + (accQK[0][0][ni][1] + bqr[ni].y) * (accQK[1][0][ni][1] + bkr[ni].y);
                s1 += (accQK[0][0][ni][2] + bqr[ni].x) * (accQK[1][0][ni][2] + bkr[ni].x)
                    + (accQK[0][0][ni][3] + bqr[ni].y) * (accQK[1][0][ni][3] + bkr[ni].y);
            }
            s0 += __shfl_xor_sync(0xffffffffu, s0, 1);
            s0 += __shfl_xor_sync(0xffffffffu, s0, 2);
            s1 += __shfl_xor_sync(0xffffffffu, s1, 1);
            s1 += __shfl_xor_sync(0xffffffffu, s1, 2);
            ev[0] = __expf(s0 * SCALEF);
            ev[1] = __expf(s1 * SCALEF);
        }

        // pass 2: V
        float accV[1][1][4][4];
        gemm_bf16<1, 1>(asB, Wv_, Wv_, accV, mbase, wn, lane);

        __syncthreads();          // all warps done reading As

        // convert staged X -> As (bf16, swizzled)
        if (hasNext) {
            cp_wait<0>();
            #pragma unroll
            for (int j = 0; j < 2; ++j) {
                int q = qs + j;
                float4 x0 = *(const float4*)(Xs + pr * 128 + q * 8);
                float4 x1 = *(const float4*)(Xs + pr * 128 + q * 8 + 4);
                uint4 u;
                u.x = pack_bf16(x0.x, x0.y); u.y = pack_bf16(x0.z, x0.w);
                u.z = pack_bf16(x1.x, x1.y); u.w = pack_bf16(x1.z, x1.w);
                *(uint4*)((char*)As + pr * 256 + ((q ^ (pr & 7)) << 4)) = u;
            }
        }

        // scatter: split-target REDG — even lanes write src, odd lanes write dst,
        // one full-warp red.v4 per (sr, ni) instead of two half-predicated ones.
        #pragma unroll
        for (int sr = 0; sr < 2; ++sr) {
            int src = srcR[sr], dst = dstR[sr];
            float w = ev[sr];
            if (tg == 0)      red_add_f(&g_den[(size_t)src * 4 + wn], w);
            else if (tg == 1) red_add_f(&g_den[(size_t)dst * 4 + wn], w);
            float* base = (tg & 1) ? (g_S + (size_t)dst * DMODEL)
                                   : (g_S + (size_t)src * DMODEL);
            #pragma unroll
            for (int ni = 0; ni < 4; ++ni) {
                int col = wn * 32 + ni * 8 + tg * 2;
                float v0 = (accV[0][0][ni][sr * 2]     + bvr[ni].x) * w;
                float v1 = (accV[0][0][ni][sr * 2 + 1] + bvr[ni].y) * w;
                float p0 = __shfl_xor_sync(0xffffffffu, v0, 1);
                float p1 = __shfl_xor_sync(0xffffffffu, v1, 1);
                int col4 = wn * 32 + ni * 8 + (tg & ~1) * 2;
                if (tg & 1) red_add_v4(base + col4, p0, p1, v0, v1);
                else        red_add_v4(base + col4, v0, v1, p0, p1);
                (void)col;
            }
        }

        __syncthreads();          // As refilled
    }
}

// ---------------- kernel 4: per-NODE Wo GEMM: T = (0.5*S/den)@Wo + 0.5*bo ----
// 64-row node tiles, bf16 core, 48KB smem -> 2 CTAs/SM, 256 thr (2m x 4n, M=2).
__global__ __launch_bounds__(256, 2)
void nodeT_kernel(const float* __restrict__ bo) {
    extern __shared__ char smc[];
    __nv_bfloat16* Ms  = (__nv_bfloat16*)smc;      // [64][128] bf16 msg tile
    __nv_bfloat16* Wo_ = Ms + 64 * 128;            // [128][128] bf16 Wo

    int tid = threadIdx.x, lane = tid & 31, warp = tid >> 5;
    int wm = warp & 1, wn = warp >> 1, gr = lane >> 2, tg = lane & 3;
    size_t n0 = (size_t)blockIdx.x * 64;
    unsigned msB = (unsigned)__cvta_generic_to_shared(Ms);

    for (int i = tid; i < 2048; i += 256)
        cp_async16((float*)Wo_ + i * 4, (const float*)g_Wb[3] + i * 4);
    cp_commit();

    {   // build tile: 4 threads per row, one head (32 cols = 4 quanta) each
        int r = tid >> 2, hd = tid & 3;
        size_t node = n0 + r;
        float d = g_den[node * 4 + hd];
        float f = (d > 0.f) ? 0.5f / d : 0.f;
        const float* Sp = g_S + node * DMODEL + hd * 32;
        #pragma unroll
        for (int j = 0; j < 4; ++j) {
            int q = hd * 4 + j;
            float4 a = *(const float4*)(Sp + j * 8);
            float4 b = *(const float4*)(Sp + j * 8 + 4);
            uint4 u;
            u.x = pack_bf16(a.x * f, a.y * f); u.y = pack_bf16(a.z * f, a.w * f);
            u.z = pack_bf16(b.x * f, b.y * f); u.w = pack_bf16(b.z * f, b.w * f);
            *(uint4*)((char*)Ms + r * 256 + ((q ^ (r & 7)) << 4)) = u;
        }
    }
    cp_wait<0>();
    __syncthreads();

    float acc[1][2][4][4];
    gemm_bf16<1, 2>(msB, Wo_, Wo_, acc, wm * 32, wn, lane);

    #pragma unroll
    for (int mi = 0; mi < 2; ++mi) {
        int r0 = wm * 32 + mi * 16 + gr;
        #pragma unroll
        for (int ni = 0; ni < 4; ++ni) {
            int col = wn * 32 + ni * 8 + tg * 2;
            float hb0 = 0.5f * __ldg(bo + col), hb1 = 0.5f * __ldg(bo + col + 1);
            *(float2*)(g_T + (n0 + r0) * DMODEL + col)     =
                make_float2(acc[0][mi][ni][0] + hb0, acc[0][mi][ni][1] + hb1);
            *(float2*)(g_T + (n0 + r0 + 8) * DMODEL + col) =
                make_float2(acc[0][mi][ni][2] + hb0, acc[0][mi][ni][3] + hb1);
        }
    }
}

// ---------------- kernel 5: edge epilogue: LN(T[src]+T[dst]+X) ---------------
// (bo folded into T during nodeT)
__global__ __launch_bounds__(256)
void epi_kernel(const void* __restrict__ idx, const float* __restrict__ X,
                const float* __restrict__ gamma, const float* __restrict__ beta,
                float* __restrict__ out) {
    int tid = threadIdx.x, lane = tid & 31;
    size_t e = (size_t)blockIdx.x * 8 + (tid >> 5);
    int is64 = g_is64;

    int src = node_of(idx, is64, e);
    int dst = node_of(idx, is64, (size_t)E_EDGES + e);

    int c = lane * 4;
    float4 ts = *(const float4*)(g_T + (size_t)src * DMODEL + c);
    float4 td = *(const float4*)(g_T + (size_t)dst * DMODEL + c);
    float4 x4 = *(const float4*)(X + e * DMODEL + c);

    float4 v;
    v.x = ts.x + td.x + x4.x;
    v.y = ts.y + td.y + x4.y;
    v.z = ts.z + td.z + x4.z;
    v.w = ts.w + td.w + x4.w;

    float s = v.x + v.y + v.z + v.w;
    float q = v.x * v.x + v.y * v.y + v.z * v.z + v.w * v.w;
    #pragma unroll
    for (int o = 16; o > 0; o >>= 1) {
        s += __shfl_xor_sync(0xffffffffu, s, o);
        q += __shfl_xor_sync(0xffffffffu, q, o);
    }
    float mu = s * (1.0f / 128.0f);
    float var = q * (1.0f / 128.0f) - mu * mu;
    float rstd = rsqrtf(var + LN_EPSF);

    float4 g4 = *(const float4*)(gamma + c);
    float4 be = *(const float4*)(beta + c);
    float4 o4;
    o4.x = (v.x - mu) * rstd * g4.x + be.x;
    o4.y = (v.y - mu) * rstd * g4.y + be.y;
    o4.z = (v.z - mu) * rstd * g4.z + be.z;
    o4.w = (v.w - mu) * rstd * g4.w + be.w;
    *(float4*)(out + e * DMODEL + c) = o4;
}

// ---------------- host -------------------------------------------------------
#define SMEM_P     ((64 * 128 + 3 * 128 * 128) * 2 + 64 * 128 * 4)   // 112KB + 32KB
#define SMEM_NODE  ((64 * 128 + 128 * 128) * 2)                       // 48KB

extern "C" void kernel_launch(void* const* d_in, const int* in_sizes, int n_in,
                              void* d_out, int out_size) {
    const float* X   = (const float*)d_in[0];
    const void*  idx = d_in[1];
    int base = 2;
    if (n_in >= 13 && in_sizes[2] == 1) base = 3;
    const float* Wq    = (const float*)d_in[base + 0];
    const float* bq    = (const float*)d_in[base + 1];
    const float* Wk    = (const float*)d_in[base + 2];
    const float* bk    = (const float*)d_in[base + 3];
    const float* Wv    = (const float*)d_in[base + 4];
    const float* bv    = (const float*)d_in[base + 5];
    const float* Wo    = (const float*)d_in[base + 6];
    const float* bo    = (const float*)d_in[base + 7];
    const float* gamma = (const float*)d_in[base + 8];
    const float* beta  = (const float*)d_in[base + 9];
    float* out = (float*)d_out;

    cudaFuncSetAttribute(fusedP_kernel, cudaFuncAttributeMaxDynamicSharedMemorySize, SMEM_P);
    cudaFuncSetAttribute(nodeT_kernel,  cudaFuncAttributeMaxDynamicSharedMemorySize, SMEM_NODE);

    detect_kernel<<<1, 32>>>((const int*)idx);
    init_kernel<<<8192, 256>>>();
    prep_kernel<<<dim3(4, 4, 4), dim3(32, 8)>>>(Wq, Wk, Wv, Wo);
    fusedP_kernel<<<PGRID, 512, SMEM_P>>>(X, idx, bq, bk, bv);
    nodeT_kernel<<<NNODES / 64, 256, SMEM_NODE>>>(bo);
    epi_kernel<<<E_EDGES / 8, 256>>>(idx, X, gamma, beta, out);
}

// round 15
// speedup vs baseline: 1.1692x; 1.0265x over previous
#include <cuda_runtime.h>
#include <cuda_bf16.h>

#define E_EDGES 262144
#define DMODEL  128
#define NNODES  65536
#define LN_EPSF 1e-5f
#define SCALEF  0.17677669529663687f   // 1/sqrt(32)
#define NTILES  4096                   // 64-edge tiles
#define PGRID   152

// ---------------- scratch (device globals; no allocations allowed) ----------
__device__ float g_S[(size_t)NNODES * DMODEL];       // sum exp(s)*V per node
__device__ float g_den[(size_t)NNODES * 4];          // sum exp(s) per node/head
__device__ float g_T[(size_t)NNODES * DMODEL];       // (0.5*S/den)@Wo + 0.5*bo
__device__ __nv_bfloat16 g_Wb[4][DMODEL][DMODEL];    // bf16, transposed, paired-k+swz
__device__ int   g_is64;

// ---------------- helpers ----------------------------------------------------
__device__ __forceinline__ void mma_bf16(float c[4], const unsigned a[4],
                                         unsigned b0, unsigned b1) {
    asm volatile(
        "mma.sync.aligned.m16n8k16.row.col.f32.bf16.bf16.f32 "
        "{%0,%1,%2,%3}, {%4,%5,%6,%7}, {%8,%9}, {%0,%1,%2,%3};"
        : "+f"(c[0]), "+f"(c[1]), "+f"(c[2]), "+f"(c[3])
        : "r"(a[0]), "r"(a[1]), "r"(a[2]), "r"(a[3]), "r"(b0), "r"(b1));
}

__device__ __forceinline__ void ldsm4(unsigned r[4], unsigned addr) {
    asm volatile("ldmatrix.sync.aligned.m8n8.x4.shared.b16 {%0,%1,%2,%3}, [%4];"
                 : "=r"(r[0]), "=r"(r[1]), "=r"(r[2]), "=r"(r[3]) : "r"(addr));
}

__device__ __forceinline__ unsigned pack_bf16(float lo, float hi) {
    __nv_bfloat162 h = __floats2bfloat162_rn(lo, hi);   // .x = lo (low 16 bits)
    return *(unsigned*)&h;
}

__device__ __forceinline__ void red_add_v4(float* p, float x, float y, float z, float w) {
    asm volatile("red.global.add.v4.f32 [%0], {%1,%2,%3,%4};"
                 :: "l"(p), "f"(x), "f"(y), "f"(z), "f"(w) : "memory");
}
__device__ __forceinline__ void red_add_f(float* p, float v) {
    asm volatile("red.global.add.f32 [%0], %1;" :: "l"(p), "f"(v) : "memory");
}

__device__ __forceinline__ void cp_async16(void* smem_dst, const void* gsrc) {
    unsigned s = (unsigned)__cvta_generic_to_shared(smem_dst);
    asm volatile("cp.async.cg.shared.global [%0], [%1], 16;" :: "r"(s), "l"(gsrc));
}
__device__ __forceinline__ void cp_commit() {
    asm volatile("cp.async.commit_group;");
}
template <int N>
__device__ __forceinline__ void cp_wait() {
    asm volatile("cp.async.wait_group %0;" :: "n"(N));
}

__device__ __forceinline__ int node_of(const void* idx, int is64, size_t pos) {
    return is64 ? (int)__ldg((const long long*)idx + pos)
                : __ldg((const int*)idx + pos);
}

__device__ __forceinline__ int swzB(int n) {        // B quantum swizzle
    return ((n & 1) << 2) | ((n >> 1) & 3);
}

// bf16 GEMM core over a 64-row A tile (bf16, 256B rows, quantum^(r&7) swizzle)
// and G weight matrices (paired-k layout). Per warp: m = 16*M rows, n32.
// A via ldmatrix.x4; B via one LDS.128 per (g,ni) covering TWO k16 steps.
template <int G, int M>
__device__ __forceinline__ void gemm_bf16(unsigned asB,
                                          const __nv_bfloat16* W0,
                                          const __nv_bfloat16* W1,
                                          float acc[G][M][4][4],
                                          int mbase, int wn, int lane) {
    const __nv_bfloat16* Wg[2] = {W0, W1};
    int tg = lane & 3, gr = lane >> 2;
    int li = lane & 7, lj = (lane >> 3) & 1, qb = lane >> 4;
    int arow = mbase + lj * 8 + li;                 // mbase multiple of 16
    int rsw = arow & 7;
    unsigned aBase = asB + (unsigned)arow * 256u;

    #pragma unroll
    for (int g = 0; g < G; ++g)
        #pragma unroll
        for (int mi = 0; mi < M; ++mi)
            #pragma unroll
            for (int ni = 0; ni < 4; ++ni)
                #pragma unroll
                for (int q = 0; q < 4; ++q) acc[g][mi][ni][q] = 0.f;

    #pragma unroll
    for (int p = 0; p < 4; ++p) {                   // k32 groups
        float4 bf[G][4];
        #pragma unroll
        for (int g = 0; g < G; ++g)
            #pragma unroll
            for (int ni = 0; ni < 4; ++ni) {
                int n = wn * 32 + ni * 8 + gr;
                bf[g][ni] = *(const float4*)((const char*)Wg[g] + n * 256 +
                              (((p * 4 + tg) ^ swzB(n)) << 4));
            }
        #pragma unroll
        for (int sh = 0; sh < 2; ++sh) {            // two k16 steps per group
            int s = p * 2 + sh;
            unsigned koff = (unsigned)(((2 * s + qb) ^ rsw) << 4);
            unsigned a[M][4];
            #pragma unroll
            for (int mi = 0; mi < M; ++mi)
                ldsm4(a[mi], aBase + (unsigned)(mi * 16 * 256) + koff);
            #pragma unroll
            for (int g = 0; g < G; ++g)
                #pragma unroll
                for (int ni = 0; ni < 4; ++ni) {
                    unsigned b0 = __float_as_uint(sh ? bf[g][ni].z : bf[g][ni].x);
                    unsigned b1 = __float_as_uint(sh ? bf[g][ni].w : bf[g][ni].y);
                    #pragma unroll
                    for (int mi = 0; mi < M; ++mi)
                        mma_bf16(acc[g][mi][ni], a[mi], b0, b1);
                }
        }
    }
}

// ---------------- kernel 0: edge_index dtype detection ----------------------
__global__ void detect_kernel(const int* __restrict__ idx) {
    if (threadIdx.x == 0) {
        int nz = 0;
        #pragma unroll 1
        for (int i = 0; i < 64; ++i) nz |= idx[2 * i + 1];
        g_is64 = (nz == 0) ? 1 : 0;
    }
}

// ---------------- kernel 1: zero init ----------------------------------------
__global__ void init_kernel() {
    size_t i = (size_t)blockIdx.x * blockDim.x + threadIdx.x;
    if (i < (size_t)NNODES * DMODEL / 4)
        ((float4*)g_S)[i] = make_float4(0.f, 0.f, 0.f, 0.f);
    if (i < (size_t)NNODES)
        ((float4*)g_den)[i] = make_float4(0.f, 0.f, 0.f, 0.f);
}

// ---------------- kernel 2: weight prep --------------------------------------
// W^T[n][k] in bf16 with paired-k permutation (within each k32 group:
// newr = ((r>>1)&3)*8 + (r>>3)*2 + (r&1)) and quantum swizzle ^swzB(n).
__global__ void prep_kernel(const float* __restrict__ Wq, const float* __restrict__ Wk,
                            const float* __restrict__ Wv, const float* __restrict__ Wo) {
    __shared__ float t[32][33];
    const float* W[4] = {Wq, Wk, Wv, Wo};
    int w = blockIdx.z, k0 = blockIdx.x * 32, n0 = blockIdx.y * 32;
    int tx = threadIdx.x, ty = threadIdx.y;      // 32 x 8
    const float* src = W[w];
    #pragma unroll
    for (int j = 0; j < 32; j += 8)
        t[ty + j][tx] = src[(k0 + ty + j) * DMODEL + n0 + tx];
    __syncthreads();
    #pragma unroll
    for (int j = 0; j < 32; j += 8) {
        int n = n0 + ty + j;
        int k = k0 + tx;
        int r = k & 31;
        int newr = ((r >> 1) & 3) * 8 + ((r >> 3) << 1) + (r & 1);
        int klog = (k & ~31) | newr;
        int kphys = ((klog >> 3) ^ swzB(n)) * 8 + (klog & 7);
        g_Wb[w][n][kphys] = __float2bfloat16(t[tx][ty + j]);
    }
}

// ---------------- kernel 3: persistent fused QKV + scores + scatter ----------
// 152 CTAs x 512 thr (16 warps). 64-edge tiles, DOUBLE-BUFFERED A (one
// __syncthreads per tile; conversion of next tile overlaps GEMM/scatter).
// Warp grid 4m x 4n, per-warp m16 x n32; Q+K pass then V pass.
__global__ __launch_bounds__(512, 1)
void fusedP_kernel(const float* __restrict__ X, const void* __restrict__ idx,
                   const float* __restrict__ bq, const float* __restrict__ bk,
                   const float* __restrict__ bv) {
    extern __shared__ char smc[];
    __nv_bfloat16* As0 = (__nv_bfloat16*)smc;              // [64][128] bf16 buf 0
    __nv_bfloat16* As1 = As0 + 64 * 128;                   // [64][128] bf16 buf 1
    __nv_bfloat16* Wq_ = As1 + 64 * 128;                   // 3 x [128][128] bf16
    __nv_bfloat16* Wk_ = Wq_ + 128 * 128;
    __nv_bfloat16* Wv_ = Wk_ + 128 * 128;
    float* Xs = (float*)(Wv_ + 128 * 128);                 // [64][128] fp32 staging

    int tid = threadIdx.x, lane = tid & 31, warp = tid >> 5;
    int wm = warp & 3, wn = warp >> 2, gr = lane >> 2, tg = lane & 3;
    int mbase = wm * 16;
    int is64 = g_is64;
    unsigned asB[2];
    asB[0] = (unsigned)__cvta_generic_to_shared(As0);
    asB[1] = (unsigned)__cvta_generic_to_shared(As1);

    // one-time: 3 weight matrices (contiguous) + first X tile into staging
    for (int i = tid; i < 6144; i += 512)
        cp_async16((float*)Wq_ + i * 4, (const float*)g_Wb + i * 4);
    {
        size_t e0 = (size_t)blockIdx.x * 64;
        for (int i = tid; i < 2048; i += 512) {
            int r = i >> 5, c = (i & 31) << 2;
            cp_async16(Xs + r * 128 + c, X + (e0 + r) * DMODEL + c);
        }
    }
    cp_commit();
    cp_wait<0>();
    __syncthreads();

    // conversion roles: thread -> (row pr, 2 quanta starting at qs)
    int pr = tid >> 3, qs = (tid & 7) * 2;
    {   // build first As (buf 0) from staging
        #pragma unroll
        for (int j = 0; j < 2; ++j) {
            int q = qs + j;
            float4 x0 = *(const float4*)(Xs + pr * 128 + q * 8);
            float4 x1 = *(const float4*)(Xs + pr * 128 + q * 8 + 4);
            uint4 u;
            u.x = pack_bf16(x0.x, x0.y); u.y = pack_bf16(x0.z, x0.w);
            u.z = pack_bf16(x1.x, x1.y); u.w = pack_bf16(x1.z, x1.w);
            *(uint4*)((char*)As0 + pr * 256 + ((q ^ (pr & 7)) << 4)) = u;
        }
    }
    __syncthreads();

    // loop-invariant bias fragments (fp32, added post-GEMM)
    float2 bqr[4], bkr[4], bvr[4];
    #pragma unroll
    for (int ni = 0; ni < 4; ++ni) {
        int col = wn * 32 + ni * 8 + tg * 2;
        bqr[ni] = make_float2(__ldg(bq + col), __ldg(bq + col + 1));
        bkr[ni] = make_float2(__ldg(bk + col), __ldg(bk + col + 1));
        bvr[ni] = make_float2(__ldg(bv + col), __ldg(bv + col + 1));
    }

    int cur = 0;
    for (int t = blockIdx.x; t < NTILES; t += PGRID) {
        size_t e0 = (size_t)t * 64;
        int tn = t + PGRID;
        bool hasNext = tn < NTILES;

        // stream next X tile (fp32) into staging while we compute
        if (hasNext) {
            size_t en = (size_t)tn * 64;
            for (int i = tid; i < 2048; i += 512) {
                int r = i >> 5, c = (i & 31) << 2;
                cp_async16(Xs + r * 128 + c, X + (en + r) * DMODEL + c);
            }
            cp_commit();
        }

        // prefetch this tile's edge indices
        int srcR[2], dstR[2];
        #pragma unroll
        for (int sr = 0; sr < 2; ++sr) {
            int row = mbase + sr * 8 + gr;
            srcR[sr] = node_of(idx, is64, e0 + row);
            dstR[sr] = node_of(idx, is64, (size_t)E_EDGES + e0 + row);
        }

        // pass 1: Q + K
        float accQK[2][1][4][4];
        gemm_bf16<2, 1>(asB[cur], Wq_, Wk_, accQK, mbase, wn, lane);

        // scores for head wn, exp
        float ev[2];
        {
            float s0 = 0.f, s1 = 0.f;
            #pragma unroll
            for (int ni = 0; ni < 4; ++ni) {
                s0 += (accQK[0][0][ni][0] + bqr[ni].x) * (accQK[1][0][ni][0] + bkr[ni].x)
                    + (accQK[0][0][ni][1] + bqr[ni].y) * (accQK[1][0][ni][1] + bkr[ni].y);
                s1 += (accQK[0][0][ni][2] + bqr[ni].x) * (accQK[1][0][ni][2] + bkr[ni].x)
                    + (accQK[0][0][ni][3] + bqr[ni].y) * (accQK[1][0][ni][3] + bkr[ni].y);
            }
            s0 += __shfl_xor_sync(0xffffffffu, s0, 1);
            s0 += __shfl_xor_sync(0xffffffffu, s0, 2);
            s1 += __shfl_xor_sync(0xffffffffu, s1, 1);
            s1 += __shfl_xor_sync(0xffffffffu, s1, 2);
            ev[0] = __expf(s0 * SCALEF);
            ev[1] = __expf(s1 * SCALEF);
        }

        // pass 2: V
        float accV[1][1][4][4];
        gemm_bf16<1, 1>(asB[cur], Wv_, Wv_, accV, mbase, wn, lane);

        // convert staged X -> OTHER A buffer (no barrier needed: its previous
        // readers all passed the last tile barrier; current tile reads buf cur)
        if (hasNext) {
            cp_wait<0>();
            char* dst = (char*)(cur ? As0 : As1);
            #pragma unroll
            for (int j = 0; j < 2; ++j) {
                int q = qs + j;
                float4 x0 = *(const float4*)(Xs + pr * 128 + q * 8);
                float4 x1 = *(const float4*)(Xs + pr * 128 + q * 8 + 4);
                uint4 u;
                u.x = pack_bf16(x0.x, x0.y); u.y = pack_bf16(x0.z, x0.w);
                u.z = pack_bf16(x1.x, x1.y); u.w = pack_bf16(x1.z, x1.w);
                *(uint4*)(dst + pr * 256 + ((q ^ (pr & 7)) << 4)) = u;
            }
        }

        // scatter: split-target REDG — even lanes write src, odd lanes write dst
        #pragma unroll
        for (int sr = 0; sr < 2; ++sr) {
            int src = srcR[sr], dst = dstR[sr];
            float w = ev[sr];
            if (tg == 0)      red_add_f(&g_den[(size_t)src * 4 + wn], w);
            else if (tg == 1) red_add_f(&g_den[(size_t)dst * 4 + wn], w);
            float* base = (tg & 1) ? (g_S + (size_t)dst * DMODEL)
                                   : (g_S + (size_t)src * DMODEL);
            #pragma unroll
            for (int ni = 0; ni < 4; ++ni) {
                float v0 = (accV[0][0][ni][sr * 2]     + bvr[ni].x) * w;
                float v1 = (accV[0][0][ni][sr * 2 + 1] + bvr[ni].y) * w;
                float p0 = __shfl_xor_sync(0xffffffffu, v0, 1);
                float p1 = __shfl_xor_sync(0xffffffffu, v1, 1);
                int col4 = wn * 32 + ni * 8 + (tg & ~1) * 2;
                if (tg & 1) red_add_v4(base + col4, p0, p1, v0, v1);
                else        red_add_v4(base + col4, v0, v1, p0, p1);
            }
        }

        __syncthreads();          // single barrier per tile
        cur ^= 1;
    }
}

// ---------------- kernel 4: per-NODE Wo GEMM: T = (0.5*S/den)@Wo + 0.5*bo ----
// 64-row node tiles, bf16 core, 48KB smem -> 2 CTAs/SM, 256 thr (2m x 4n, M=2).
__global__ __launch_bounds__(256, 2)
void nodeT_kernel(const float* __restrict__ bo) {
    extern __shared__ char smc[];
    __nv_bfloat16* Ms  = (__nv_bfloat16*)smc;      // [64][128] bf16 msg tile
    __nv_bfloat16* Wo_ = Ms + 64 * 128;            // [128][128] bf16 Wo

    int tid = threadIdx.x, lane = tid & 31, warp = tid >> 5;
    int wm = warp & 1, wn = warp >> 1, gr = lane >> 2, tg = lane & 3;
    size_t n0 = (size_t)blockIdx.x * 64;
    unsigned msB = (unsigned)__cvta_generic_to_shared(Ms);

    for (int i = tid; i < 2048; i += 256)
        cp_async16((float*)Wo_ + i * 4, (const float*)g_Wb[3] + i * 4);
    cp_commit();

    {   // build tile: 4 threads per row, one head (32 cols = 4 quanta) each
        int r = tid >> 2, hd = tid & 3;
        size_t node = n0 + r;
        float d = g_den[node * 4 + hd];
        float f = (d > 0.f) ? 0.5f / d : 0.f;
        const float* Sp = g_S + node * DMODEL + hd * 32;
        #pragma unroll
        for (int j = 0; j < 4; ++j) {
            int q = hd * 4 + j;
            float4 a = *(const float4*)(Sp + j * 8);
            float4 b = *(const float4*)(Sp + j * 8 + 4);
            uint4 u;
            u.x = pack_bf16(a.x * f, a.y * f); u.y = pack_bf16(a.z * f, a.w * f);
            u.z = pack_bf16(b.x * f, b.y * f); u.w = pack_bf16(b.z * f, b.w * f);
            *(uint4*)((char*)Ms + r * 256 + ((q ^ (r & 7)) << 4)) = u;
        }
    }
    cp_wait<0>();
    __syncthreads();

    float acc[1][2][4][4];
    gemm_bf16<1, 2>(msB, Wo_, Wo_, acc, wm * 32, wn, lane);

    #pragma unroll
    for (int mi = 0; mi < 2; ++mi) {
        int r0 = wm * 32 + mi * 16 + gr;
        #pragma unroll
        for (int ni = 0; ni < 4; ++ni) {
            int col = wn * 32 + ni * 8 + tg * 2;
            float hb0 = 0.5f * __ldg(bo + col), hb1 = 0.5f * __ldg(bo + col + 1);
            *(float2*)(g_T + (n0 + r0) * DMODEL + col)     =
                make_float2(acc[0][mi][ni][0] + hb0, acc[0][mi][ni][1] + hb1);
            *(float2*)(g_T + (n0 + r0 + 8) * DMODEL + col) =
                make_float2(acc[0][mi][ni][2] + hb0, acc[0][mi][ni][3] + hb1);
        }
    }
}

// ---------------- kernel 5: edge epilogue: LN(T[src]+T[dst]+X) ---------------
__global__ __launch_bounds__(256)
void epi_kernel(const void* __restrict__ idx, const float* __restrict__ X,
                const float* __restrict__ gamma, const float* __restrict__ beta,
                float* __restrict__ out) {
    int tid = threadIdx.x, lane = tid & 31;
    size_t e = (size_t)blockIdx.x * 8 + (tid >> 5);
    int is64 = g_is64;

    int src = node_of(idx, is64, e);
    int dst = node_of(idx, is64, (size_t)E_EDGES + e);

    int c = lane * 4;
    float4 ts = *(const float4*)(g_T + (size_t)src * DMODEL + c);
    float4 td = *(const float4*)(g_T + (size_t)dst * DMODEL + c);
    float4 x4 = *(const float4*)(X + e * DMODEL + c);

    float4 v;
    v.x = ts.x + td.x + x4.x;
    v.y = ts.y + td.y + x4.y;
    v.z = ts.z + td.z + x4.z;
    v.w = ts.w + td.w + x4.w;

    float s = v.x + v.y + v.z + v.w;
    float q = v.x * v.x + v.y * v.y + v.z * v.z + v.w * v.w;
    #pragma unroll
    for (int o = 16; o > 0; o >>= 1) {
        s += __shfl_xor_sync(0xffffffffu, s, o);
        q += __shfl_xor_sync(0xffffffffu, q, o);
    }
    float mu = s * (1.0f / 128.0f);
    float var = q * (1.0f / 128.0f) - mu * mu;
    float rstd = rsqrtf(var + LN_EPSF);

    float4 g4 = *(const float4*)(gamma + c);
    float4 be = *(const float4*)(beta + c);
    float4 o4;
    o4.x = (v.x - mu) * rstd * g4.x + be.x;
    o4.y = (v.y - mu) * rstd * g4.y + be.y;
    o4.z = (v.z - mu) * rstd * g4.z + be.z;
    o4.w = (v.w - mu) * rstd * g4.w + be.w;
    *(float4*)(out + e * DMODEL + c) = o4;
}

// ---------------- host -------------------------------------------------------
#define SMEM_P     ((2 * 64 * 128 + 3 * 128 * 128) * 2 + 64 * 128 * 4)  // 128KB+32KB
#define SMEM_NODE  ((64 * 128 + 128 * 128) * 2)                          // 48KB

extern "C" void kernel_launch(void* const* d_in, const int* in_sizes, int n_in,
                              void* d_out, int out_size) {
    const float* X   = (const float*)d_in[0];
    const void*  idx = d_in[1];
    int base = 2;
    if (n_in >= 13 && in_sizes[2] == 1) base = 3;
    const float* Wq    = (const float*)d_in[base + 0];
    const float* bq    = (const float*)d_in[base + 1];
    const float* Wk    = (const float*)d_in[base + 2];
    const float* bk    = (const float*)d_in[base + 3];
    const float* Wv    = (const float*)d_in[base + 4];
    const float* bv    = (const float*)d_in[base + 5];
    const float* Wo    = (const float*)d_in[base + 6];
    const float* bo    = (const float*)d_in[base + 7];
    const float* gamma = (const float*)d_in[base + 8];
    const float* beta  = (const float*)d_in[base + 9];
    float* out = (float*)d_out;

    cudaFuncSetAttribute(fusedP_kernel, cudaFuncAttributeMaxDynamicSharedMemorySize, SMEM_P);
    cudaFuncSetAttribute(nodeT_kernel,  cudaFuncAttributeMaxDynamicSharedMemorySize, SMEM_NODE);

    detect_kernel<<<1, 32>>>((const int*)idx);
    init_kernel<<<8192, 256>>>();
    prep_kernel<<<dim3(4, 4, 4), dim3(32, 8)>>>(Wq, Wk, Wv, Wo);
    fusedP_kernel<<<PGRID, 512, SMEM_P>>>(X, idx, bq, bk, bv);
    nodeT_kernel<<<NNODES / 64, 256, SMEM_NODE>>>(bo);
    epi_kernel<<<E_EDGES / 8, 256>>>(idx, X, gamma, beta, out);
}